// round 9
// baseline (speedup 1.0000x reference)
#include <cuda_runtime.h>
#include <stdint.h>

#define Bn 32
#define In 1152
#define On 10
#define Dn 16
#define Hn 10
#define Sn 922
#define NT0 256
#define NT1 512
#define NW1 (NT1 / 32)           // 16 warps
#define NBO (Bn * On)            // 320 (b,o) tasks

// ---- global scratch (device globals: allocation-free) ----
__device__ float g_uprime[(size_t)NBO * In * Dn];   // [bo][i][d]  5.9 MB
__device__ float g_w [(size_t)NBO * In];            // ||u_i||     1.5 MB
__device__ float g_w2[(size_t)NBO * In];            // ||u_i||^2   1.5 MB

// sqrt via single MUFU.RSQ: x*rsqrt(x). clamp keeps 0 -> 0.
__device__ __forceinline__ float fsqrt_mufu(float x) {
    return x * __frsqrt_rn(fmaxf(x, 1e-35f));
}

// ================= K0: transpose + norms =================
__global__ void __launch_bounds__(NT0)
prep_kernel(const float* __restrict__ up)
{
    int e = blockIdx.x * NT0 + threadIdx.x;          // float4 id over whole tensor
    int q = e & 3;
    int t = e >> 2;                                  // (b*I + i)*O + o
    int o = t % On;
    int bi = t / On;
    int i = bi % In;
    int b = bi / In;
    float4 v = reinterpret_cast<const float4*>(up)[e];
    int bo = b * On + o;
    reinterpret_cast<float4*>(g_uprime)[((size_t)bo * In + i) * 4 + q] = v;
    float s = v.x * v.x + v.y * v.y + v.z * v.z + v.w * v.w;
    s += __shfl_xor_sync(0xffffffffu, s, 1);
    s += __shfl_xor_sync(0xffffffffu, s, 2);
    if (q == 0) {
        size_t off = (size_t)bo * In + i;
        g_w2[off] = s;
        g_w[off]  = fsqrt_mufu(s);
    }
}

// ================= K1: main (512 threads, 2 CTAs/SM) =================
struct SmemK1 {
    unsigned rbits[In];            // 10-bit hypothesis mask per i
    float npart[NW1 * Dn * Hn];    // per-warp num partials [w][d][h]
    float dpart[NW1 * Hn];
    float lpart[NW1 * Hn];
    float Mu[Hn * Dn];             // Mu[h][d]
    float mm[Hn];
    float denom[Hn];
    float losses[Hn];
    int besth;
    int idx_is64;
};

__global__ void __launch_bounds__(NT1, 2)
ransac_kernel(const int* __restrict__ sidx32, float* __restrict__ out)
{
    __shared__ SmemK1 sm;
    const int tid = threadIdx.x;
    const int bo = blockIdx.x;
    const int b = bo / On, o = bo % On;
    const int lane = tid & 31, wrp = tid >> 5;

    const float*  uP  = g_uprime + (size_t)bo * In * Dn;
    const float4* u4  = reinterpret_cast<const float4*>(uP);
    const float*  wP  = g_w  + (size_t)bo * In;
    const float*  w2P = g_w2 + (size_t)bo * In;

    // ---- init: zero masks; sniff index dtype ----
    for (int i = tid; i < In; i += NT1) sm.rbits[i] = 0u;
    if (tid == 0) {
        int all0 = 1;                       // int64 -> odd words all 0 (idx < 1152)
        #pragma unroll
        for (int k = 0; k < 8; k++) all0 &= (sidx32[2 * k + 1] == 0);
        sm.idx_is64 = all0;
    }
    __syncthreads();
    const int is64 = sm.idx_is64;

    // ---- Phase C: scatter sample_idx -> rbits ----
    {
        const size_t base = (size_t)b * Sn * On * Hn + (size_t)o * Hn;
        for (int e = tid; e < Sn * Hn; e += NT1) {          // 18 iters
            int s = e / Hn, h = e - s * Hn;
            size_t eo = base + (size_t)s * (On * Hn) + h;
            int i = is64 ? sidx32[eo << 1] : sidx32[eo];    // low word (LE)
            if ((unsigned)i < (unsigned)In)
                atomicOr(&sm.rbits[i], 1u << h);
        }
    }
    __syncthreads();

    // ---- Phase D: num[d][h] = sum_i r*w*u ; denom[h] = sum_i r*w ----
    // d-pair split: lane handles dims {d8, d8+8}, 64 i-partitions.
    {
        const int d8 = tid & 7, ip = tid >> 3;              // 0..63
        float acc0[Hn], acc1[Hn], dloc[Hn];
        #pragma unroll
        for (int h = 0; h < Hn; h++) { acc0[h] = 0.f; acc1[h] = 0.f; dloc[h] = 0.f; }
        #pragma unroll 3
        for (int i = ip; i < In; i += 64) {                 // 18 exact iters
            float ua = uP[i * Dn + d8];
            float ub = uP[i * Dn + d8 + 8];
            unsigned bits = sm.rbits[i];
            float wi = wP[i];
            #pragma unroll
            for (int h = 0; h < Hn; h++) {
                float m = ((bits >> h) & 1u) ? wi : 0.0f;
                acc0[h] = fmaf(m, ua, acc0[h]);
                acc1[h] = fmaf(m, ub, acc1[h]);
                dloc[h] += m;
            }
        }
        // reduce over the 4 ip-groups within each warp (d8 preserved)
        #pragma unroll
        for (int off = 8; off <= 16; off <<= 1) {
            #pragma unroll
            for (int h = 0; h < Hn; h++) {
                acc0[h] += __shfl_xor_sync(0xffffffffu, acc0[h], off);
                acc1[h] += __shfl_xor_sync(0xffffffffu, acc1[h], off);
                dloc[h] += __shfl_xor_sync(0xffffffffu, dloc[h], off);
            }
        }
        if (lane < 8) {
            #pragma unroll
            for (int h = 0; h < Hn; h++) {
                sm.npart[(wrp * Dn + d8) * Hn + h]     = acc0[h];
                sm.npart[(wrp * Dn + d8 + 8) * Hn + h] = acc1[h];
            }
            if (lane == 0)
                #pragma unroll
                for (int h = 0; h < Hn; h++) sm.dpart[wrp * Hn + h] = dloc[h];
        }
    }
    __syncthreads();

    // ---- Phase E: final reduce -> Mu, mm ----
    float numreg = 0.f;
    int dd = 0, hh = 0;
    if (tid < 160) {
        dd = tid / Hn; hh = tid - dd * Hn;
        #pragma unroll
        for (int w = 0; w < NW1; w++) numreg += sm.npart[(w * Dn + dd) * Hn + hh];
    } else if (tid < 160 + Hn) {
        int h = tid - 160;
        float s = 0.f;
        #pragma unroll
        for (int w = 0; w < NW1; w++) s += sm.dpart[w * Hn + h];
        sm.denom[h] = s;
    }
    __syncthreads();
    if (tid < 160) sm.Mu[hh * Dn + dd] = numreg / sm.denom[hh];
    __syncthreads();
    if (tid < Hn) {
        float s = 0.f;
        #pragma unroll
        for (int d = 0; d < Dn; d++) { float m = sm.Mu[tid * Dn + d]; s = fmaf(m, m, s); }
        sm.mm[tid] = s;
    }
    __syncthreads();

    // ---- Phase F: losses[h] = sum_i sqrt(w2[i] - 2*dot(u_i,Mu_h) + mm[h]) ----
    {
        float lloc[Hn], mmr[Hn];
        #pragma unroll
        for (int h = 0; h < Hn; h++) { lloc[h] = 0.f; mmr[h] = sm.mm[h]; }
        const float4* mu4 = reinterpret_cast<const float4*>(sm.Mu);
        for (int i = tid; i < In; i += NT1) {               // 2-3 iters
            float4 a  = u4[i * 4 + 0], b4 = u4[i * 4 + 1];
            float4 c  = u4[i * 4 + 2], d4 = u4[i * 4 + 3];
            float ww2 = w2P[i];
            #pragma unroll
            for (int h = 0; h < Hn; h++) {
                float4 m0 = mu4[h * 4 + 0], m1 = mu4[h * 4 + 1];
                float4 m2 = mu4[h * 4 + 2], m3 = mu4[h * 4 + 3];
                float d0 = a.x * m0.x;
                float d1 = a.y * m0.y;
                d0 = fmaf(a.z, m0.z, d0);   d1 = fmaf(a.w, m0.w, d1);
                d0 = fmaf(b4.x, m1.x, d0);  d1 = fmaf(b4.y, m1.y, d1);
                d0 = fmaf(b4.z, m1.z, d0);  d1 = fmaf(b4.w, m1.w, d1);
                d0 = fmaf(c.x, m2.x, d0);   d1 = fmaf(c.y, m2.y, d1);
                d0 = fmaf(c.z, m2.z, d0);   d1 = fmaf(c.w, m2.w, d1);
                d0 = fmaf(d4.x, m3.x, d0);  d1 = fmaf(d4.y, m3.y, d1);
                d0 = fmaf(d4.z, m3.z, d0);  d1 = fmaf(d4.w, m3.w, d1);
                float s = fmaf(-2.0f, d0 + d1, ww2 + mmr[h]);
                s = fmaxf(s, 0.0f);
                lloc[h] += fsqrt_mufu(s);
            }
        }
        #pragma unroll
        for (int off = 1; off <= 16; off <<= 1)
            #pragma unroll
            for (int h = 0; h < Hn; h++)
                lloc[h] += __shfl_xor_sync(0xffffffffu, lloc[h], off);
        if (lane == 0)
            #pragma unroll
            for (int h = 0; h < Hn; h++) sm.lpart[wrp * Hn + h] = lloc[h];
    }
    __syncthreads();
    if (tid < Hn) {
        float s = 0.f;
        #pragma unroll
        for (int w = 0; w < NW1; w++) s += sm.lpart[w * Hn + tid];
        sm.losses[tid] = s;
    }
    __syncthreads();
    if (tid == 0) {
        int best = 0; float bv = sm.losses[0];
        #pragma unroll
        for (int h = 1; h < Hn; h++)
            if (sm.losses[h] < bv) { bv = sm.losses[h]; best = h; }
        sm.besth = best;
    }
    __syncthreads();

    // ---- output: v[b,o,:] = Mu[:, besth] ----
    if (tid < Dn)
        out[(size_t)bo * Dn + tid] = sm.Mu[sm.besth * Dn + tid];
}

extern "C" void kernel_launch(void* const* d_in, const int* in_sizes, int n_in,
                              void* d_out, int out_size)
{
    const float* up;
    const int* si;
    if (in_sizes[0] == Bn * In * On * Dn) {
        up = (const float*)d_in[0];
        si = (const int*)d_in[1];
    } else {
        up = (const float*)d_in[1];
        si = (const int*)d_in[0];
    }
    float* out = (float*)d_out;

    // K0: transpose + norms.  total float4 = 320*1152*4 = 1,474,560 = 5760 * 256
    prep_kernel<<<(NBO * In * 4) / NT0, NT0>>>(up);
    // K1: main per-(b,o) kernel, 512 threads
    ransac_kernel<<<NBO, NT1>>>(si, out);
}

// round 12
// speedup vs baseline: 1.4676x; 1.4676x over previous
#include <cuda_runtime.h>
#include <stdint.h>

#define Bn 32
#define In 1152
#define On 10
#define Dn 16
#define Hn 10
#define Sn 922
#define NBO (Bn * On)            // 320 (b,o) tasks
#define NCHUNK 4                 // i-chunks for Mu GEMV
#define CHI (In / NCHUNK)        // 288

// ---- global scratch (device globals: allocation-free) ----
__device__ float    g_uprime[(size_t)NBO * In * Dn];   // [bo][i][d]  23.6 MB
__device__ float    g_w  [(size_t)NBO * In];
__device__ float    g_w2 [(size_t)NBO * In];
__device__ unsigned g_rbits[(size_t)NBO * In];
__device__ float    g_npart[(size_t)NBO * NCHUNK * Dn * Hn];
__device__ float    g_dpart[(size_t)NBO * NCHUNK * Hn];
__device__ float    g_Mu [(size_t)NBO * Hn * Dn];      // [bo][h][d]
__device__ float    g_mm [(size_t)NBO * Hn];
__device__ float    g_losses[(size_t)NBO * Hn];

__device__ __forceinline__ float fsqrt_mufu(float x) {
    return x * __frsqrt_rn(fmaxf(x, 1e-35f));
}

// ============ K0: transpose + norms + zero rbits ============
__global__ void __launch_bounds__(256)
k0_prep(const float* __restrict__ up)
{
    int e = blockIdx.x * 256 + threadIdx.x;          // float4 id
    if (e < NBO * In) g_rbits[e] = 0u;
    int q = e & 3;
    int t = e >> 2;                                  // (b*I + i)*O + o
    int o = t % On;
    int bi = t / On;
    int i = bi % In;
    int b = bi / In;
    float4 v = reinterpret_cast<const float4*>(up)[e];
    int bo = b * On + o;
    reinterpret_cast<float4*>(g_uprime)[((size_t)bo * In + i) * 4 + q] = v;
    float s = v.x * v.x + v.y * v.y + v.z * v.z + v.w * v.w;
    s += __shfl_xor_sync(0xffffffffu, s, 1);
    s += __shfl_xor_sync(0xffffffffu, s, 2);
    if (q == 0) {
        size_t off = (size_t)bo * In + i;
        g_w2[off] = s;
        g_w[off]  = fsqrt_mufu(s);
    }
}

// ============ K1: scatter sample_idx -> global rbits ============
// element offset in sample_idx is exactly e (layout b,s,o,h with h fastest)
__global__ void __launch_bounds__(256)
k1_scatter(const int* __restrict__ sidx32)
{
    __shared__ int s_is64;
    if (threadIdx.x == 0) {
        int all0 = 1;                    // int64 -> odd words all 0 (idx < 1152)
        #pragma unroll
        for (int k = 0; k < 8; k++) all0 &= (sidx32[2 * k + 1] == 0);
        s_is64 = all0;
    }
    __syncthreads();
    int e = blockIdx.x * 256 + threadIdx.x;          // < Bn*Sn*On*Hn = 2,950,400
    int i = s_is64 ? sidx32[(size_t)e << 1] : sidx32[e];
    int h = e % Hn;
    int o = (e / Hn) % On;
    int b = e / (Sn * On * Hn);
    if ((unsigned)i < (unsigned)In)
        atomicOr(&g_rbits[(size_t)(b * On + o) * In + i], 1u << h);
}

// ============ K2: Mu GEMV partials over i-chunks ============
__global__ void __launch_bounds__(128)
k2_gemv(int dummy)
{
    __shared__ float s_np[4 * Dn * Hn];   // [warp][d][h]
    __shared__ float s_dp[4 * Hn];
    const int tid = threadIdx.x;
    const int bo = blockIdx.x, chunk = blockIdx.y;
    const int lane = tid & 31, wrp = tid >> 5;
    const int d8 = tid & 7, ip = tid >> 3;           // 0..15
    const float* uP = g_uprime + (size_t)bo * In * Dn;
    const float* wP = g_w + (size_t)bo * In;
    const unsigned* rP = g_rbits + (size_t)bo * In;
    const int ibase = chunk * CHI;

    float acc0[Hn], acc1[Hn], dloc[Hn];
    #pragma unroll
    for (int h = 0; h < Hn; h++) { acc0[h] = 0.f; acc1[h] = 0.f; dloc[h] = 0.f; }
    #pragma unroll 3
    for (int k = 0; k < CHI / 16; k++) {             // 18 iters
        int i = ibase + ip + k * 16;
        float ua = uP[i * Dn + d8];
        float ub = uP[i * Dn + d8 + 8];
        unsigned bits = rP[i];
        float wi = wP[i];
        #pragma unroll
        for (int h = 0; h < Hn; h++) {
            float m = ((bits >> h) & 1u) ? wi : 0.0f;
            acc0[h] = fmaf(m, ua, acc0[h]);
            acc1[h] = fmaf(m, ub, acc1[h]);
            dloc[h] += m;
        }
    }
    // reduce over the 4 ip-groups within each warp (d8 preserved)
    #pragma unroll
    for (int off = 8; off <= 16; off <<= 1) {
        #pragma unroll
        for (int h = 0; h < Hn; h++) {
            acc0[h] += __shfl_xor_sync(0xffffffffu, acc0[h], off);
            acc1[h] += __shfl_xor_sync(0xffffffffu, acc1[h], off);
            dloc[h] += __shfl_xor_sync(0xffffffffu, dloc[h], off);
        }
    }
    if (lane < 8) {
        #pragma unroll
        for (int h = 0; h < Hn; h++) {
            s_np[(wrp * Dn + d8) * Hn + h]     = acc0[h];
            s_np[(wrp * Dn + d8 + 8) * Hn + h] = acc1[h];
        }
        if (lane == 0)
            #pragma unroll
            for (int h = 0; h < Hn; h++) s_dp[wrp * Hn + h] = dloc[h];
    }
    __syncthreads();
    // FIXED epilogue: 128 threads cover all 160 npart entries + 10 dpart entries
    for (int t = tid; t < Dn * Hn; t += 128) {
        float s = s_np[t] + s_np[Dn * Hn + t]
                + s_np[2 * Dn * Hn + t] + s_np[3 * Dn * Hn + t];
        g_npart[((size_t)bo * NCHUNK + chunk) * Dn * Hn + t] = s;
    }
    if (tid < Hn) {
        float s = s_dp[tid] + s_dp[Hn + tid] + s_dp[2 * Hn + tid] + s_dp[3 * Hn + tid];
        g_dpart[((size_t)bo * NCHUNK + chunk) * Hn + tid] = s;
    }
}

// ============ K3: finalize Mu, mm ============
__global__ void __launch_bounds__(192)
k3_mu(int dummy)
{
    __shared__ float sden[Hn];
    __shared__ __align__(16) float sMu[Hn * Dn];     // [h][d]
    const int tid = threadIdx.x;
    const int bo = blockIdx.x;
    if (tid < Hn) {
        float s = 0.f;
        #pragma unroll
        for (int c = 0; c < NCHUNK; c++)
            s += g_dpart[((size_t)bo * NCHUNK + c) * Hn + tid];
        sden[tid] = s;
    }
    __syncthreads();
    if (tid < Dn * Hn) {
        int d = tid / Hn, h = tid - d * Hn;          // npart layout [d][h]
        float s = 0.f;
        #pragma unroll
        for (int c = 0; c < NCHUNK; c++)
            s += g_npart[((size_t)bo * NCHUNK + c) * Dn * Hn + tid];
        float mu = s / sden[h];
        sMu[h * Dn + d] = mu;
        g_Mu[((size_t)bo * Hn + h) * Dn + d] = mu;
    }
    __syncthreads();
    if (tid < Hn) {
        float s = 0.f;
        #pragma unroll
        for (int d = 0; d < Dn; d++) { float m = sMu[tid * Dn + d]; s = fmaf(m, m, s); }
        g_mm[(size_t)bo * Hn + tid] = s;
    }
}

// ============ K4: losses[bo][h], one CTA per (bo,h) ============
__global__ void __launch_bounds__(128)
k4_loss(int dummy)
{
    __shared__ __align__(16) float sMu[Dn];
    __shared__ float smm;
    __shared__ float spart[4];
    const int tid = threadIdx.x;
    const int bo = blockIdx.x, h = blockIdx.y;
    if (tid < Dn) sMu[tid] = g_Mu[((size_t)bo * Hn + h) * Dn + tid];
    if (tid == Dn) smm = g_mm[(size_t)bo * Hn + h];
    __syncthreads();
    const float4* u4  = reinterpret_cast<const float4*>(g_uprime + (size_t)bo * In * Dn);
    const float*  w2P = g_w2 + (size_t)bo * In;
    float4 m0 = reinterpret_cast<const float4*>(sMu)[0];
    float4 m1 = reinterpret_cast<const float4*>(sMu)[1];
    float4 m2 = reinterpret_cast<const float4*>(sMu)[2];
    float4 m3 = reinterpret_cast<const float4*>(sMu)[3];
    const float mmv = smm;

    float lloc = 0.f;
    #pragma unroll
    for (int k = 0; k < In / 128; k++) {             // 9 exact iters
        int i = tid + k * 128;
        float4 a  = u4[i * 4 + 0], b4 = u4[i * 4 + 1];
        float4 c  = u4[i * 4 + 2], d4 = u4[i * 4 + 3];
        float ww2 = w2P[i];
        float d0 = a.x * m0.x;
        float d1 = a.y * m0.y;
        d0 = fmaf(a.z, m0.z, d0);   d1 = fmaf(a.w, m0.w, d1);
        d0 = fmaf(b4.x, m1.x, d0);  d1 = fmaf(b4.y, m1.y, d1);
        d0 = fmaf(b4.z, m1.z, d0);  d1 = fmaf(b4.w, m1.w, d1);
        d0 = fmaf(c.x, m2.x, d0);   d1 = fmaf(c.y, m2.y, d1);
        d0 = fmaf(c.z, m2.z, d0);   d1 = fmaf(c.w, m2.w, d1);
        d0 = fmaf(d4.x, m3.x, d0);  d1 = fmaf(d4.y, m3.y, d1);
        d0 = fmaf(d4.z, m3.z, d0);  d1 = fmaf(d4.w, m3.w, d1);
        float s = fmaf(-2.0f, d0 + d1, ww2 + mmv);
        lloc += fsqrt_mufu(fmaxf(s, 0.0f));
    }
    #pragma unroll
    for (int off = 1; off <= 16; off <<= 1)
        lloc += __shfl_xor_sync(0xffffffffu, lloc, off);
    if ((tid & 31) == 0) spart[tid >> 5] = lloc;
    __syncthreads();
    if (tid == 0)
        g_losses[(size_t)bo * Hn + h] = spart[0] + spart[1] + spart[2] + spart[3];
}

// ============ K5: argmin + gather output ============
__global__ void __launch_bounds__(32)
k5_pick(float* __restrict__ out)
{
    const int bo = blockIdx.x;
    const int lane = threadIdx.x;
    int best = 0;
    if (lane == 0) {
        float bv = g_losses[(size_t)bo * Hn];
        #pragma unroll
        for (int h = 1; h < Hn; h++) {
            float v = g_losses[(size_t)bo * Hn + h];
            if (v < bv) { bv = v; best = h; }
        }
    }
    best = __shfl_sync(0xffffffffu, best, 0);
    if (lane < Dn)
        out[(size_t)bo * Dn + lane] = g_Mu[((size_t)bo * Hn + best) * Dn + lane];
}

extern "C" void kernel_launch(void* const* d_in, const int* in_sizes, int n_in,
                              void* d_out, int out_size)
{
    const float* up;
    const int* si;
    if (in_sizes[0] == Bn * In * On * Dn) {
        up = (const float*)d_in[0];
        si = (const int*)d_in[1];
    } else {
        up = (const float*)d_in[1];
        si = (const int*)d_in[0];
    }
    float* out = (float*)d_out;

    k0_prep   <<<(NBO * In * 4) / 256, 256>>>(up);            // 5760 CTAs
    k1_scatter<<<(Bn * Sn * On * Hn) / 256, 256>>>(si);       // 11525 CTAs
    k2_gemv   <<<dim3(NBO, NCHUNK), 128>>>(0);                // 1280 CTAs
    k3_mu     <<<NBO, 192>>>(0);
    k4_loss   <<<dim3(NBO, Hn), 128>>>(0);                    // 3200 CTAs
    k5_pick   <<<NBO, 32>>>(out);
}

// round 13
// speedup vs baseline: 1.5144x; 1.0319x over previous
#include <cuda_runtime.h>
#include <stdint.h>

#define Bn 32
#define In 1152
#define On 10
#define Dn 16
#define Hn 10
#define Sn 922
#define NBO (Bn * On)            // 320 (b,o) tasks
#define NCHUNK 4                 // i-chunks for Mu GEMV
#define CHI (In / NCHUNK)        // 288
#define PREP_BLKS ((NBO * In * 4) / 256)              // 5760
#define SCAT_BLKS ((Bn * Sn * On * Hn) / 256)         // 11525 (exact)

// ---- global scratch (device globals: allocation-free, zero at load) ----
__device__ float    g_uprime[(size_t)NBO * In * Dn];   // [bo][i][d]  23.6 MB
__device__ float    g_w  [(size_t)NBO * In];
__device__ float    g_w2 [(size_t)NBO * In];
__device__ unsigned g_rbits[(size_t)NBO * In];         // INVARIANT: zero at kernel_launch entry
__device__ float    g_npart[(size_t)NBO * NCHUNK * Dn * Hn];
__device__ float    g_dpart[(size_t)NBO * NCHUNK * Hn];
__device__ float    g_Mu [(size_t)NBO * Hn * Dn];      // [bo][h][d]
__device__ float    g_mm [(size_t)NBO * Hn];
__device__ float    g_losses[(size_t)NBO * Hn];
__device__ unsigned g_tickB[NBO];                      // INVARIANT: zero at entry
__device__ unsigned g_tickC[NBO];                      // INVARIANT: zero at entry

__device__ __forceinline__ float fsqrt_mufu(float x) {
    return x * __frsqrt_rn(fmaxf(x, 1e-35f));
}

// ============ KA: [prep-blocks] transpose+norms  ||  [scatter-blocks] rbits ============
__global__ void __launch_bounds__(256)
kA_prep_scatter(const float* __restrict__ up, const int* __restrict__ sidx32)
{
    const int tid = threadIdx.x;
    if (blockIdx.x < PREP_BLKS) {
        // ---- transpose + norms (coalesced float4 over whole u tensor) ----
        int e = blockIdx.x * 256 + tid;              // float4 id
        int q = e & 3;
        int t = e >> 2;                              // (b*I + i)*O + o
        int o = t % On;
        int bi = t / On;
        int i = bi % In;
        int b = bi / In;
        float4 v = reinterpret_cast<const float4*>(up)[e];
        int bo = b * On + o;
        reinterpret_cast<float4*>(g_uprime)[((size_t)bo * In + i) * 4 + q] = v;
        float s = v.x * v.x + v.y * v.y + v.z * v.z + v.w * v.w;
        s += __shfl_xor_sync(0xffffffffu, s, 1);
        s += __shfl_xor_sync(0xffffffffu, s, 2);
        if (q == 0) {
            size_t off = (size_t)bo * In + i;
            g_w2[off] = s;
            g_w[off]  = fsqrt_mufu(s);
        }
    } else {
        // ---- scatter: element offset in sample_idx is exactly e (h fastest) ----
        __shared__ int s_is64;
        if (tid == 0) {
            int all0 = 1;                // int64 -> odd words all 0 (idx < 1152)
            #pragma unroll
            for (int k = 0; k < 8; k++) all0 &= (sidx32[2 * k + 1] == 0);
            s_is64 = all0;
        }
        __syncthreads();
        int e = (blockIdx.x - PREP_BLKS) * 256 + tid;    // < 2,950,400
        int i = s_is64 ? sidx32[(size_t)e << 1] : sidx32[e];
        int h = e % Hn;
        int o = (e / Hn) % On;
        int b = e / (Sn * On * Hn);
        if ((unsigned)i < (unsigned)In)
            atomicOr(&g_rbits[(size_t)(b * On + o) * In + i], 1u << h);
    }
}

// ============ KB: Mu GEMV partials + ticket-fused finalize ============
__global__ void __launch_bounds__(128)
kB_gemv(int dummy)
{
    __shared__ float s_np[4 * Dn * Hn];   // [warp][d][h]
    __shared__ float s_dp[4 * Hn];
    __shared__ float sden[Hn];
    __shared__ float sMuF[Hn * Dn];
    __shared__ int s_last;
    const int tid = threadIdx.x;
    const int bo = blockIdx.x, chunk = blockIdx.y;
    const int lane = tid & 31, wrp = tid >> 5;
    const int d8 = tid & 7, ip = tid >> 3;           // 0..15
    const float* uP = g_uprime + (size_t)bo * In * Dn;
    const float* wP = g_w + (size_t)bo * In;
    const unsigned* rP = g_rbits + (size_t)bo * In;
    const int ibase = chunk * CHI;

    float acc0[Hn], acc1[Hn], dloc[Hn];
    #pragma unroll
    for (int h = 0; h < Hn; h++) { acc0[h] = 0.f; acc1[h] = 0.f; dloc[h] = 0.f; }
    #pragma unroll 3
    for (int k = 0; k < CHI / 16; k++) {             // 18 iters
        int i = ibase + ip + k * 16;
        float ua = uP[i * Dn + d8];
        float ub = uP[i * Dn + d8 + 8];
        unsigned bits = rP[i];
        float wi = wP[i];
        #pragma unroll
        for (int h = 0; h < Hn; h++) {
            float m = ((bits >> h) & 1u) ? wi : 0.0f;
            acc0[h] = fmaf(m, ua, acc0[h]);
            acc1[h] = fmaf(m, ub, acc1[h]);
            dloc[h] += m;
        }
    }
    #pragma unroll
    for (int off = 8; off <= 16; off <<= 1) {
        #pragma unroll
        for (int h = 0; h < Hn; h++) {
            acc0[h] += __shfl_xor_sync(0xffffffffu, acc0[h], off);
            acc1[h] += __shfl_xor_sync(0xffffffffu, acc1[h], off);
            dloc[h] += __shfl_xor_sync(0xffffffffu, dloc[h], off);
        }
    }
    if (lane < 8) {
        #pragma unroll
        for (int h = 0; h < Hn; h++) {
            s_np[(wrp * Dn + d8) * Hn + h]     = acc0[h];
            s_np[(wrp * Dn + d8 + 8) * Hn + h] = acc1[h];
        }
        if (lane == 0)
            #pragma unroll
            for (int h = 0; h < Hn; h++) s_dp[wrp * Hn + h] = dloc[h];
    }
    __syncthreads();
    for (int t = tid; t < Dn * Hn; t += 128) {
        float s = s_np[t] + s_np[Dn * Hn + t]
                + s_np[2 * Dn * Hn + t] + s_np[3 * Dn * Hn + t];
        g_npart[((size_t)bo * NCHUNK + chunk) * Dn * Hn + t] = s;
    }
    if (tid < Hn) {
        float s = s_dp[tid] + s_dp[Hn + tid] + s_dp[2 * Hn + tid] + s_dp[3 * Hn + tid];
        g_dpart[((size_t)bo * NCHUNK + chunk) * Hn + tid] = s;
    }

    // ---- ticket: last chunk-CTA of this bo finalizes Mu, mm ----
    __threadfence();
    __syncthreads();
    if (tid == 0) {
        unsigned old = atomicAdd(&g_tickB[bo], 1u);
        s_last = (old == NCHUNK - 1);
    }
    __syncthreads();
    if (!s_last) return;
    if (tid == 0) g_tickB[bo] = 0u;                  // reset for next replay
    if (tid < Hn) {
        float s = 0.f;
        #pragma unroll
        for (int c = 0; c < NCHUNK; c++)
            s += g_dpart[((size_t)bo * NCHUNK + c) * Hn + tid];
        sden[tid] = s;
    }
    __syncthreads();
    for (int t = tid; t < Dn * Hn; t += 128) {       // t = d*Hn + h
        int d = t / Hn, h = t - d * Hn;
        float s = 0.f;
        #pragma unroll
        for (int c = 0; c < NCHUNK; c++)
            s += g_npart[((size_t)bo * NCHUNK + c) * Dn * Hn + t];
        float mu = s / sden[h];
        sMuF[h * Dn + d] = mu;
        g_Mu[((size_t)bo * Hn + h) * Dn + d] = mu;
    }
    __syncthreads();
    if (tid < Hn) {
        float s = 0.f;
        #pragma unroll
        for (int d = 0; d < Dn; d++) { float m = sMuF[tid * Dn + d]; s = fmaf(m, m, s); }
        g_mm[(size_t)bo * Hn + tid] = s;
    }
}

// ============ KC: losses per (bo,h) + rbits re-zero + ticket-fused argmin/gather ============
__global__ void __launch_bounds__(128)
kC_loss(float* __restrict__ out)
{
    __shared__ __align__(16) float sMu[Dn];
    __shared__ float smm;
    __shared__ float spart[4];
    __shared__ int s_last;
    const int tid = threadIdx.x;
    const int bo = blockIdx.x, h = blockIdx.y;
    if (tid < Dn) sMu[tid] = g_Mu[((size_t)bo * Hn + h) * Dn + tid];
    if (tid == Dn) smm = g_mm[(size_t)bo * Hn + h];

    // re-zero this CTA's rbits slice (restores KA's entry invariant; not read after KB)
    {
        int st = (h * In) / Hn, en = ((h + 1) * In) / Hn;   // ~116 entries
        for (int i = st + tid; i < en; i += 128)
            g_rbits[(size_t)bo * In + i] = 0u;
    }
    __syncthreads();
    const float4* u4  = reinterpret_cast<const float4*>(g_uprime + (size_t)bo * In * Dn);
    const float*  w2P = g_w2 + (size_t)bo * In;
    float4 m0 = reinterpret_cast<const float4*>(sMu)[0];
    float4 m1 = reinterpret_cast<const float4*>(sMu)[1];
    float4 m2 = reinterpret_cast<const float4*>(sMu)[2];
    float4 m3 = reinterpret_cast<const float4*>(sMu)[3];
    const float mmv = smm;

    float lloc = 0.f;
    #pragma unroll
    for (int k = 0; k < In / 128; k++) {             // 9 exact iters
        int i = tid + k * 128;
        float4 a  = u4[i * 4 + 0], b4 = u4[i * 4 + 1];
        float4 c  = u4[i * 4 + 2], d4 = u4[i * 4 + 3];
        float ww2 = w2P[i];
        float d0 = a.x * m0.x;
        float d1 = a.y * m0.y;
        d0 = fmaf(a.z, m0.z, d0);   d1 = fmaf(a.w, m0.w, d1);
        d0 = fmaf(b4.x, m1.x, d0);  d1 = fmaf(b4.y, m1.y, d1);
        d0 = fmaf(b4.z, m1.z, d0);  d1 = fmaf(b4.w, m1.w, d1);
        d0 = fmaf(c.x, m2.x, d0);   d1 = fmaf(c.y, m2.y, d1);
        d0 = fmaf(c.z, m2.z, d0);   d1 = fmaf(c.w, m2.w, d1);
        d0 = fmaf(d4.x, m3.x, d0);  d1 = fmaf(d4.y, m3.y, d1);
        d0 = fmaf(d4.z, m3.z, d0);  d1 = fmaf(d4.w, m3.w, d1);
        float s = fmaf(-2.0f, d0 + d1, ww2 + mmv);
        lloc += fsqrt_mufu(fmaxf(s, 0.0f));
    }
    #pragma unroll
    for (int off = 1; off <= 16; off <<= 1)
        lloc += __shfl_xor_sync(0xffffffffu, lloc, off);
    if ((tid & 31) == 0) spart[tid >> 5] = lloc;
    __syncthreads();
    if (tid == 0)
        g_losses[(size_t)bo * Hn + h] = spart[0] + spart[1] + spart[2] + spart[3];

    // ---- ticket: last h-CTA of this bo does argmin + gather ----
    __threadfence();
    __syncthreads();
    if (tid == 0) {
        unsigned old = atomicAdd(&g_tickC[bo], 1u);
        s_last = (old == Hn - 1);
    }
    __syncthreads();
    if (!s_last) return;
    if (tid == 0) g_tickC[bo] = 0u;                  // reset for next replay
    __shared__ int s_best;
    if (tid == 0) {
        int best = 0; float bv = g_losses[(size_t)bo * Hn];
        #pragma unroll
        for (int hh = 1; hh < Hn; hh++) {            // fixed order -> deterministic
            float v = g_losses[(size_t)bo * Hn + hh];
            if (v < bv) { bv = v; best = hh; }
        }
        s_best = best;
    }
    __syncthreads();
    if (tid < Dn)
        out[(size_t)bo * Dn + tid] = g_Mu[((size_t)bo * Hn + s_best) * Dn + tid];
}

extern "C" void kernel_launch(void* const* d_in, const int* in_sizes, int n_in,
                              void* d_out, int out_size)
{
    const float* up;
    const int* si;
    if (in_sizes[0] == Bn * In * On * Dn) {
        up = (const float*)d_in[0];
        si = (const int*)d_in[1];
    } else {
        up = (const float*)d_in[1];
        si = (const int*)d_in[0];
    }
    float* out = (float*)d_out;

    kA_prep_scatter<<<PREP_BLKS + SCAT_BLKS, 256>>>(up, si);  // 17285 CTAs
    kB_gemv        <<<dim3(NBO, NCHUNK), 128>>>(0);           // 1280 CTAs
    kC_loss        <<<dim3(NBO, Hn), 128>>>(out);             // 3200 CTAs
}